// round 3
// baseline (speedup 1.0000x reference)
#include <cuda_runtime.h>

// SPADE: InstanceNorm2d(affine=False) + per-pixel class-conditional affine.
// x[8,128,256,256] f32, segmap[8,20,256,256] f32, weight/bias[20,128] f32.
//
// R3 structure: per-image launch chaining for L2 reuse of x.
//   argmax (once)  -> uchar class map (L2-resident, 512 KB)
//   for n in 0..7: stats_n (reads x_n, leaves it in L2)
//                  apply_n (re-reads x_n from L2, writes out_n streaming)

#define N_   8
#define C_   128
#define H_   256
#define W_   256
#define L_   20
#define HW_  (H_ * W_)      // 65536
#define NC_  (N_ * C_)      // 1024
#define EPS_ 1e-5f

// Two partial (sum, sumsq) per (n,c) plane — deterministic (no atomics).
__device__ float2 g_part[NC_ * 2];
// Per-pixel argmax class id.
__device__ unsigned char g_cls[N_ * HW_];   // 512 KB scratch

// ---------------------------------------------------------------------------
// Kernel 1: per-pixel argmax over 20 segmap planes -> uchar map.
// Streaming loads (__ldcs) so segmap does not pollute L2.
// ---------------------------------------------------------------------------
__global__ void __launch_bounds__(256) spade_argmax_kernel(const float* __restrict__ seg) {
    const int idx = blockIdx.x * 256 + threadIdx.x;     // over N*HW/4
    const int n   = idx / (HW_ / 4);
    const int p4  = idx - n * (HW_ / 4);
    const float4* __restrict__ s =
        reinterpret_cast<const float4*>(seg + (size_t)n * L_ * HW_) + p4;

    float4 best = __ldcs(s);
    int b0 = 0, b1 = 0, b2 = 0, b3 = 0;
    #pragma unroll
    for (int l = 1; l < L_; l++) {
        float4 v = __ldcs(s + (size_t)l * (HW_ / 4));
        if (v.x > best.x) { best.x = v.x; b0 = l; }
        if (v.y > best.y) { best.y = v.y; b1 = l; }
        if (v.z > best.z) { best.z = v.z; b2 = l; }
        if (v.w > best.w) { best.w = v.w; b3 = l; }
    }
    *reinterpret_cast<uchar4*>(g_cls + (size_t)n * HW_ + p4 * 4) =
        make_uchar4((unsigned char)b0, (unsigned char)b1,
                    (unsigned char)b2, (unsigned char)b3);
}

// ---------------------------------------------------------------------------
// Kernel 2: partial stats for ONE image. 2 blocks per channel plane
// (grid 256). Plain cached loads -> x_n stays resident in L2 for apply_n.
// ---------------------------------------------------------------------------
__global__ void __launch_bounds__(256) spade_stats_kernel(const float* __restrict__ x, int n) {
    const int b    = blockIdx.x;          // 0..255
    const int c    = b >> 1;
    const int half = b & 1;
    const float4* __restrict__ p =
        reinterpret_cast<const float4*>(x + (size_t)(n * C_ + c) * HW_) + half * (HW_ / 8);

    float s = 0.f, s2 = 0.f;
    #pragma unroll 8
    for (int i = threadIdx.x; i < HW_ / 8; i += 256) {   // 8192 float4 per half
        float4 v = __ldg(p + i);
        s  += (v.x + v.y) + (v.z + v.w);
        s2 += v.x * v.x + v.y * v.y + v.z * v.z + v.w * v.w;
    }

    #pragma unroll
    for (int o = 16; o > 0; o >>= 1) {
        s  += __shfl_down_sync(0xFFFFFFFFu, s,  o);
        s2 += __shfl_down_sync(0xFFFFFFFFu, s2, o);
    }

    __shared__ float ss[8], ss2[8];
    const int wid = threadIdx.x >> 5, lid = threadIdx.x & 31;
    if (lid == 0) { ss[wid] = s; ss2[wid] = s2; }
    __syncthreads();

    if (threadIdx.x == 0) {
        float ts = 0.f, ts2 = 0.f;
        #pragma unroll
        for (int i = 0; i < 8; i++) { ts += ss[i]; ts2 += ss2[i]; }
        g_part[(n * C_ + c) * 2 + half] = make_float2(ts, ts2);
    }
}

// ---------------------------------------------------------------------------
// Kernel 3: normalize + class affine for ONE image.
// Block = 256 threads (thread = float4): 4-row slab x 256 cols, CGRP=32
// channels. Grid = 64 slabs * 4 cgroups = 256.
// x reads: __ldcs (last use, evict-first; hits L2 from stats_n).
// out writes: __stcs (streaming, don't evict x).
// (w,b) in padded smem (stride 33 float2): divergent-cls gather <=2-way
// bank conflicted.
// ---------------------------------------------------------------------------
#define CGRP 32
#define WB_STRIDE 33

__global__ void __launch_bounds__(256) spade_apply_kernel(
    const float* __restrict__ x,
    const float* __restrict__ wgt,
    const float* __restrict__ bia,
    float* __restrict__ out,
    int n)
{
    __shared__ float2 s_wb[L_ * WB_STRIDE];
    __shared__ float2 s_ms[CGRP];

    const int b    = blockIdx.x;          // 0..255
    const int cg   = b & 3;
    const int slab = b >> 2;              // 0..63
    const int c0   = cg * CGRP;
    const int h0   = slab << 2;
    const int tid  = threadIdx.x;

    // Stage merged (w,b) for this channel group.
    for (int i = tid; i < L_ * CGRP; i += 256) {
        int l = i >> 5, c = i & (CGRP - 1);
        s_wb[l * WB_STRIDE + c] =
            make_float2(__ldg(wgt + l * C_ + c0 + c), __ldg(bia + l * C_ + c0 + c));
    }
    // Finalize stats from the two deterministic partials.
    if (tid < CGRP) {
        const int idx = (n * C_ + c0 + tid) * 2;
        float2 p0 = g_part[idx], p1 = g_part[idx + 1];
        const float inv_hw = 1.0f / (float)HW_;
        float mean = (p0.x + p1.x) * inv_hw;
        float var  = (p0.y + p1.y) * inv_hw - mean * mean;
        if (var < 0.f) var = 0.f;
        s_ms[tid] = make_float2(mean, rsqrtf(var + EPS_));
    }

    // This thread's 4 pixels.
    const int r    = tid >> 6;
    const int col4 = (tid & 63) << 2;
    const int pix  = (h0 + r) * W_ + col4;

    const uchar4 cl = *reinterpret_cast<const uchar4*>(g_cls + (size_t)n * HW_ + pix);
    const int i0 = cl.x * WB_STRIDE, i1 = cl.y * WB_STRIDE,
              i2 = cl.z * WB_STRIDE, i3 = cl.w * WB_STRIDE;
    __syncthreads();

    const float* __restrict__ xn = x   + (size_t)(n * C_ + c0) * HW_ + pix;
    float*       __restrict__ on = out + (size_t)(n * C_ + c0) * HW_ + pix;

    #pragma unroll 1
    for (int c = 0; c < CGRP; c += 4) {
        float4 v[4];
        #pragma unroll
        for (int u = 0; u < 4; u++)
            v[u] = __ldcs(reinterpret_cast<const float4*>(xn + (size_t)(c + u) * HW_));
        #pragma unroll
        for (int u = 0; u < 4; u++) {
            const int cc = c + u;
            const float2 ms = s_ms[cc];
            const float2 w0 = s_wb[i0 + cc];
            const float2 w1 = s_wb[i1 + cc];
            const float2 w2 = s_wb[i2 + cc];
            const float2 w3 = s_wb[i3 + cc];
            float4 o;
            o.x = fmaf((v[u].x - ms.x) * ms.y, w0.x, w0.y);
            o.y = fmaf((v[u].y - ms.x) * ms.y, w1.x, w1.y);
            o.z = fmaf((v[u].z - ms.x) * ms.y, w2.x, w2.y);
            o.w = fmaf((v[u].w - ms.x) * ms.y, w3.x, w3.y);
            __stcs(reinterpret_cast<float4*>(on + (size_t)cc * HW_), o);
        }
    }
}

// ---------------------------------------------------------------------------
extern "C" void kernel_launch(void* const* d_in, const int* in_sizes, int n_in,
                              void* d_out, int out_size) {
    const float* x   = (const float*)d_in[0];
    const float* seg = (const float*)d_in[1];
    const float* wgt = (const float*)d_in[2];
    const float* bia = (const float*)d_in[3];
    float* out = (float*)d_out;

    spade_argmax_kernel<<<(N_ * HW_ / 4) / 256, 256>>>(seg);
    for (int n = 0; n < N_; n++) {
        spade_stats_kernel<<<256, 256>>>(x, n);
        spade_apply_kernel<<<256, 256>>>(x, wgt, bia, out, n);
    }
}

// round 4
// speedup vs baseline: 1.1099x; 1.1099x over previous
#include <cuda_runtime.h>

// SPADE: InstanceNorm2d(affine=False) + per-pixel class-conditional affine.
// x[8,128,256,256] f32, segmap[8,20,256,256] f32, weight/bias[20,128] f32.
//
// R4: single persistent kernel, 512 co-resident blocks, phase-pipelined:
//   phase 0:   argmax + stats(img 0)
//   phase k:   stats(img k)  ||  apply(img k-1)   (x_{k-1} read hits L2)
//   tail:      apply(img 7)
// Grid barrier between phases (monotonic generation counter -> safe across
// CUDA-graph replays with zero host-side state).

#define N_   8
#define C_   128
#define H_   256
#define W_   256
#define L_   20
#define HW_  (H_ * W_)      // 65536
#define EPS_ 1e-5f

#define GRID    512
#define THREADS 256
#define CGRP    16          // channels per apply work item (8 groups)
#define WB_STRIDE 17        // padded smem stride (<=2-way bank conflicts)

// Partial (sum, sumsq): 4 segments per plane, double-buffered by image parity.
__device__ float2 g_part[2][C_ * 4];
// Per-pixel argmax class id.
__device__ unsigned char g_cls[N_ * HW_];   // 512 KB
// Grid barrier state. g_gen is monotonic across launches/replays.
__device__ unsigned int g_count = 0;
__device__ unsigned int g_gen   = 0;

// ---------------------------------------------------------------------------
__device__ __forceinline__ void grid_barrier() {
    __syncthreads();
    if (threadIdx.x == 0) {
        unsigned int snap = *(volatile unsigned int*)&g_gen;
        __threadfence();                       // release our writes
        unsigned int t = atomicAdd(&g_count, 1u);
        if (t == GRID - 1) {
            atomicExch(&g_count, 0u);          // reset for next episode
            __threadfence();
            atomicAdd(&g_gen, 1u);             // release everyone
        } else {
            while (*(volatile unsigned int*)&g_gen == snap) { __nanosleep(64); }
        }
        __threadfence();                       // acquire
    }
    __syncthreads();
}

// ---------------------------------------------------------------------------
// Stats for image n: block b -> plane c = b>>2, segment b&3 (16384 floats).
// Plain cached loads: fills L2 for the apply of this image next phase.
// ---------------------------------------------------------------------------
__device__ __forceinline__ void do_stats(const float* __restrict__ x, int n, int b) {
    const int c   = b >> 2;
    const int seg = b & 3;
    const float4* __restrict__ p =
        reinterpret_cast<const float4*>(x + (size_t)(n * C_ + c) * HW_) + seg * 4096;

    float s = 0.f, s2 = 0.f;
    #pragma unroll
    for (int i = 0; i < 16; i++) {             // 16 * 256 = 4096 float4
        float4 v = __ldg(p + i * 256 + threadIdx.x);
        s  += (v.x + v.y) + (v.z + v.w);
        s2 += v.x * v.x + v.y * v.y + v.z * v.z + v.w * v.w;
    }
    #pragma unroll
    for (int o = 16; o > 0; o >>= 1) {
        s  += __shfl_down_sync(0xFFFFFFFFu, s,  o);
        s2 += __shfl_down_sync(0xFFFFFFFFu, s2, o);
    }
    __shared__ float ss[8], ss2[8];
    const int wid = threadIdx.x >> 5, lid = threadIdx.x & 31;
    if (lid == 0) { ss[wid] = s; ss2[wid] = s2; }
    __syncthreads();
    if (threadIdx.x == 0) {
        float ts = 0.f, ts2 = 0.f;
        #pragma unroll
        for (int i = 0; i < 8; i++) { ts += ss[i]; ts2 += ss2[i]; }
        g_part[n & 1][c * 4 + seg] = make_float2(ts, ts2);
    }
    __syncthreads();
}

// ---------------------------------------------------------------------------
// Argmax over 20 segmap planes. Thread-item = 4 adjacent pixels (float4).
// Streaming loads so segmap doesn't evict x_0.
// ---------------------------------------------------------------------------
__device__ __forceinline__ void do_argmax(const float* __restrict__ seg, int b) {
    const int idx = b * THREADS + threadIdx.x;           // 0 .. 131071
    const int n   = idx >> 14;                           // / (HW/4)
    const int p4  = idx & 16383;
    const float4* __restrict__ s =
        reinterpret_cast<const float4*>(seg + (size_t)n * L_ * HW_) + p4;

    float4 best = __ldcs(s);
    int b0 = 0, b1 = 0, b2 = 0, b3 = 0;
    #pragma unroll
    for (int l = 1; l < L_; l++) {
        float4 v = __ldcs(s + (size_t)l * (HW_ / 4));
        if (v.x > best.x) { best.x = v.x; b0 = l; }
        if (v.y > best.y) { best.y = v.y; b1 = l; }
        if (v.z > best.z) { best.z = v.z; b2 = l; }
        if (v.w > best.w) { best.w = v.w; b3 = l; }
    }
    *reinterpret_cast<uchar4*>(g_cls + (size_t)n * HW_ + p4 * 4) =
        make_uchar4((unsigned char)b0, (unsigned char)b1,
                    (unsigned char)b2, (unsigned char)b3);
}

// ---------------------------------------------------------------------------
// Apply for image n: block b -> cgroup = b&7 (16 channels), slab = b>>3
// (4 rows). Thread = float4 of pixels. x reads hit L2; writes stream.
// ---------------------------------------------------------------------------
__device__ __forceinline__ void do_apply(
    const float* __restrict__ x, float* __restrict__ out,
    const float2* __restrict__ s_wb, int n, int b)
{
    __shared__ float2 s_ms[CGRP];

    const int cg   = b & 7;
    const int slab = b >> 3;                  // 0..63
    const int c0   = cg * CGRP;
    const int h0   = slab << 2;
    const int tid  = threadIdx.x;

    if (tid < CGRP) {
        const float2* pp = &g_part[n & 1][(c0 + tid) * 4];
        float ts  = ((pp[0].x + pp[1].x) + (pp[2].x + pp[3].x));
        float ts2 = ((pp[0].y + pp[1].y) + (pp[2].y + pp[3].y));
        const float inv_hw = 1.0f / (float)HW_;
        float mean = ts * inv_hw;
        float var  = ts2 * inv_hw - mean * mean;
        if (var < 0.f) var = 0.f;
        s_ms[tid] = make_float2(mean, rsqrtf(var + EPS_));
    }

    const int r    = tid >> 6;
    const int col4 = (tid & 63) << 2;
    const int pix  = (h0 + r) * W_ + col4;

    const uchar4 cl = *reinterpret_cast<const uchar4*>(g_cls + (size_t)n * HW_ + pix);
    const int i0 = cl.x * WB_STRIDE, i1 = cl.y * WB_STRIDE,
              i2 = cl.z * WB_STRIDE, i3 = cl.w * WB_STRIDE;
    __syncthreads();

    const float* __restrict__ xn = x   + (size_t)(n * C_ + c0) * HW_ + pix;
    float*       __restrict__ on = out + (size_t)(n * C_ + c0) * HW_ + pix;

    #pragma unroll 1
    for (int c = 0; c < CGRP; c += 4) {
        float4 v[4];
        #pragma unroll
        for (int u = 0; u < 4; u++)
            v[u] = __ldg(reinterpret_cast<const float4*>(xn + (size_t)(c + u) * HW_));
        #pragma unroll
        for (int u = 0; u < 4; u++) {
            const int cc = c + u;
            const float2 ms = s_ms[cc];
            const float2 w0 = s_wb[i0 + cc];
            const float2 w1 = s_wb[i1 + cc];
            const float2 w2 = s_wb[i2 + cc];
            const float2 w3 = s_wb[i3 + cc];
            float4 o;
            o.x = fmaf((v[u].x - ms.x) * ms.y, w0.x, w0.y);
            o.y = fmaf((v[u].y - ms.x) * ms.y, w1.x, w1.y);
            o.z = fmaf((v[u].z - ms.x) * ms.y, w2.x, w2.y);
            o.w = fmaf((v[u].w - ms.x) * ms.y, w3.x, w3.y);
            __stcs(reinterpret_cast<float4*>(on + (size_t)cc * HW_), o);
        }
    }
    __syncthreads();
}

// ---------------------------------------------------------------------------
__global__ void __launch_bounds__(THREADS, 4) spade_fused_kernel(
    const float* __restrict__ x,
    const float* __restrict__ seg,
    const float* __restrict__ wgt,
    const float* __restrict__ bia,
    float* __restrict__ out)
{
    __shared__ float2 s_wb[L_ * WB_STRIDE];   // merged (w,b), this block's cgroup

    const int b  = blockIdx.x;
    const int c0 = (b & 7) * CGRP;            // this block's apply channel group

    // Stage (w,b) once — same cgroup every image.
    for (int i = threadIdx.x; i < L_ * CGRP; i += THREADS) {
        int l = i / CGRP, c = i - l * CGRP;
        s_wb[l * WB_STRIDE + c] =
            make_float2(__ldg(wgt + l * C_ + c0 + c), __ldg(bia + l * C_ + c0 + c));
    }

    // Phase 0: argmax + stats(0)
    do_argmax(seg, b);
    do_stats(x, 0, b);
    grid_barrier();

    // Phases 1..7: stats(k) || apply(k-1)
    for (int k = 1; k < N_; k++) {
        do_stats(x, k, b);
        do_apply(x, out, s_wb, k - 1, b);
        grid_barrier();
    }

    // Tail: apply(7)
    do_apply(x, out, s_wb, N_ - 1, b);
}

// ---------------------------------------------------------------------------
extern "C" void kernel_launch(void* const* d_in, const int* in_sizes, int n_in,
                              void* d_out, int out_size) {
    const float* x   = (const float*)d_in[0];
    const float* seg = (const float*)d_in[1];
    const float* wgt = (const float*)d_in[2];
    const float* bia = (const float*)d_in[3];
    float* out = (float*)d_out;

    spade_fused_kernel<<<GRID, THREADS>>>(x, seg, wgt, bia, out);
}

// round 5
// speedup vs baseline: 1.2358x; 1.1134x over previous
#include <cuda_runtime.h>

// SPADE: InstanceNorm2d(affine=False) + per-pixel class-conditional affine.
// x[8,128,256,256] f32, segmap[8,20,256,256] f32, weight/bias[20,128] f32.
//
// R5: persistent kernel, 512 co-resident blocks, ROLE-SPLIT per phase:
//   phase 0:   [176 blocks] stats(img 0)   || [336 blocks] argmax (streaming)
//   phase k:   [176 blocks] stats(img k)   || [336 blocks] apply(img k-1)
//   tail:      [336 blocks] apply(img 7)
// stats fills L2 with x_k while apply concurrently drains x_{k-1} from L2
// (evict-first reads, streaming writes). 8 grid barriers, monotonic-gen
// (CUDA-graph-replay safe, no host state).

#define N_   8
#define C_   128
#define H_   256
#define W_   256
#define L_   20
#define HW_  (H_ * W_)      // 65536
#define EPS_ 1e-5f

#define GRID    512
#define THREADS 256
#define SB      176          // stats blocks
#define AB      (GRID - SB)  // 336 apply blocks
#define CGRP    8            // channels per apply item
#define WB_STRIDE 129        // full-table padded stride (<=2-way LDS conflicts)

// Quarter-plane partials (sum, sumsq), double-buffered by image parity.
__device__ float2 g_part[2][C_ * 4];
// Per-pixel argmax class id.
__device__ unsigned char g_cls[N_ * HW_];   // 512 KB
// Grid barrier: g_gen monotonic across launches/replays.
__device__ unsigned int g_count = 0;
__device__ unsigned int g_gen   = 0;

// ---------------------------------------------------------------------------
__device__ __forceinline__ void grid_barrier() {
    __syncthreads();
    if (threadIdx.x == 0) {
        unsigned int snap = *(volatile unsigned int*)&g_gen;
        __threadfence();
        unsigned int t = atomicAdd(&g_count, 1u);
        if (t == GRID - 1) {
            atomicExch(&g_count, 0u);
            __threadfence();
            atomicAdd(&g_gen, 1u);
        } else {
            while (*(volatile unsigned int*)&g_gen == snap) { __nanosleep(64); }
        }
        __threadfence();
    }
    __syncthreads();
}

// ---------------------------------------------------------------------------
// Stats item s in [0,512): plane c = s>>2, quarter q = s&3 (16384 floats).
// Normal cached loads -> x_n resident in L2 for next phase's apply.
// ---------------------------------------------------------------------------
__device__ __forceinline__ void do_stats_item(const float* __restrict__ x, int n, int s) {
    const int c = s >> 2;
    const int q = s & 3;
    const float4* __restrict__ p =
        reinterpret_cast<const float4*>(x + (size_t)(n * C_ + c) * HW_) + q * 4096;

    float sm = 0.f, s2 = 0.f;
    #pragma unroll
    for (int i = 0; i < 16; i++) {             // 16 * 256 = 4096 float4
        float4 v = __ldg(p + i * 256 + threadIdx.x);
        sm += (v.x + v.y) + (v.z + v.w);
        s2 += v.x * v.x + v.y * v.y + v.z * v.z + v.w * v.w;
    }
    #pragma unroll
    for (int o = 16; o > 0; o >>= 1) {
        sm += __shfl_down_sync(0xFFFFFFFFu, sm, o);
        s2 += __shfl_down_sync(0xFFFFFFFFu, s2, o);
    }
    __shared__ float ss[8], ss2[8];
    const int wid = threadIdx.x >> 5, lid = threadIdx.x & 31;
    if (lid == 0) { ss[wid] = sm; ss2[wid] = s2; }
    __syncthreads();
    if (threadIdx.x == 0) {
        float ts = 0.f, ts2 = 0.f;
        #pragma unroll
        for (int i = 0; i < 8; i++) { ts += ss[i]; ts2 += ss2[i]; }
        g_part[n & 1][c * 4 + q] = make_float2(ts, ts2);
    }
    __syncthreads();
}

// ---------------------------------------------------------------------------
// Argmax item i in [0,512): 1024 consecutive pixels (thread = float4).
// Streaming loads so segmap doesn't evict x_0.
// ---------------------------------------------------------------------------
__device__ __forceinline__ void do_argmax_item(const float* __restrict__ seg, int i) {
    const int idx = i * THREADS + threadIdx.x;           // 0 .. 131071
    const int n   = idx >> 14;                           // / (HW/4)
    const int p4  = idx & 16383;
    const float4* __restrict__ s =
        reinterpret_cast<const float4*>(seg + (size_t)n * L_ * HW_) + p4;

    float4 best = __ldcs(s);
    int b0 = 0, b1 = 0, b2 = 0, b3 = 0;
    #pragma unroll
    for (int l = 1; l < L_; l++) {
        float4 v = __ldcs(s + (size_t)l * (HW_ / 4));
        if (v.x > best.x) { best.x = v.x; b0 = l; }
        if (v.y > best.y) { best.y = v.y; b1 = l; }
        if (v.z > best.z) { best.z = v.z; b2 = l; }
        if (v.w > best.w) { best.w = v.w; b3 = l; }
    }
    *reinterpret_cast<uchar4*>(g_cls + (size_t)n * HW_ + p4 * 4) =
        make_uchar4((unsigned char)b0, (unsigned char)b1,
                    (unsigned char)b2, (unsigned char)b3);
}

// ---------------------------------------------------------------------------
// Apply item a in [0,1024): cgroup = a&15 (8 channels), slab = a>>4 (4 rows).
// x reads: __ldcs (last use, L2 hit from previous phase's stats).
// out writes: __stcs (streaming).
// ---------------------------------------------------------------------------
__device__ __forceinline__ void do_apply_item(
    const float* __restrict__ x, float* __restrict__ out,
    const float2* __restrict__ s_wb, const float2* __restrict__ s_ms,
    int n, int a)
{
    const int c0  = (a & 15) * CGRP;
    const int h0  = (a >> 4) << 2;
    const int tid = threadIdx.x;

    const int r    = tid >> 6;
    const int col4 = (tid & 63) << 2;
    const int pix  = (h0 + r) * W_ + col4;

    const uchar4 cl = *reinterpret_cast<const uchar4*>(g_cls + (size_t)n * HW_ + pix);
    const int i0 = cl.x * WB_STRIDE + c0, i1 = cl.y * WB_STRIDE + c0,
              i2 = cl.z * WB_STRIDE + c0, i3 = cl.w * WB_STRIDE + c0;

    const float* __restrict__ xn = x   + (size_t)(n * C_ + c0) * HW_ + pix;
    float*       __restrict__ on = out + (size_t)(n * C_ + c0) * HW_ + pix;

    float4 v[CGRP];
    #pragma unroll
    for (int c = 0; c < CGRP; c++)             // 8 outstanding 16B loads
        v[c] = __ldcs(reinterpret_cast<const float4*>(xn + (size_t)c * HW_));
    #pragma unroll
    for (int c = 0; c < CGRP; c++) {
        const float2 ms = s_ms[c0 + c];
        const float2 w0 = s_wb[i0 + c];
        const float2 w1 = s_wb[i1 + c];
        const float2 w2 = s_wb[i2 + c];
        const float2 w3 = s_wb[i3 + c];
        float4 o;
        o.x = fmaf((v[c].x - ms.x) * ms.y, w0.x, w0.y);
        o.y = fmaf((v[c].y - ms.x) * ms.y, w1.x, w1.y);
        o.z = fmaf((v[c].z - ms.x) * ms.y, w2.x, w2.y);
        o.w = fmaf((v[c].w - ms.x) * ms.y, w3.x, w3.y);
        __stcs(reinterpret_cast<float4*>(on + (size_t)c * HW_), o);
    }
}

// ---------------------------------------------------------------------------
__global__ void __launch_bounds__(THREADS, 4) spade_fused_kernel(
    const float* __restrict__ x,
    const float* __restrict__ seg,
    const float* __restrict__ wgt,
    const float* __restrict__ bia,
    float* __restrict__ out)
{
    __shared__ float2 s_wb[L_ * WB_STRIDE];   // full merged (w,b) table, 20.6 KB
    __shared__ float2 s_ms[C_];               // per-channel (mean, invstd)

    const int b = blockIdx.x;
    const bool is_stats = (b < SB);
    const int b2 = b - SB;

    // Stage the full (w,b) table once.
    for (int i = threadIdx.x; i < L_ * C_; i += THREADS) {
        int l = i >> 7, c = i & (C_ - 1);
        s_wb[l * WB_STRIDE + c] = make_float2(__ldg(wgt + i), __ldg(bia + i));
    }

    // Phase 0: stats(0) || argmax
    if (is_stats) {
        for (int s = b; s < 512; s += SB) do_stats_item(x, 0, s);
    } else {
        for (int i = b2; i < 512; i += AB) do_argmax_item(seg, i);
    }
    grid_barrier();

    // Phases 1..7: stats(k) || apply(k-1)
    for (int k = 1; k < N_; k++) {
        if (is_stats) {
            for (int s = b; s < 512; s += SB) do_stats_item(x, k, s);
        } else {
            // Finalize stats for image k-1 into smem (once per phase).
            if (threadIdx.x < C_) {
                const float2* pp = &g_part[(k - 1) & 1][threadIdx.x * 4];
                float ts  = (pp[0].x + pp[1].x) + (pp[2].x + pp[3].x);
                float ts2 = (pp[0].y + pp[1].y) + (pp[2].y + pp[3].y);
                const float inv_hw = 1.0f / (float)HW_;
                float mean = ts * inv_hw;
                float var  = ts2 * inv_hw - mean * mean;
                if (var < 0.f) var = 0.f;
                s_ms[threadIdx.x] = make_float2(mean, rsqrtf(var + EPS_));
            }
            __syncthreads();
            for (int a = b2; a < 1024; a += AB)
                do_apply_item(x, out, s_wb, s_ms, k - 1, a);
        }
        grid_barrier();
    }

    // Tail: apply(7)
    if (!is_stats) {
        if (threadIdx.x < C_) {
            const float2* pp = &g_part[(N_ - 1) & 1][threadIdx.x * 4];
            float ts  = (pp[0].x + pp[1].x) + (pp[2].x + pp[3].x);
            float ts2 = (pp[0].y + pp[1].y) + (pp[2].y + pp[3].y);
            const float inv_hw = 1.0f / (float)HW_;
            float mean = ts * inv_hw;
            float var  = ts2 * inv_hw - mean * mean;
            if (var < 0.f) var = 0.f;
            s_ms[threadIdx.x] = make_float2(mean, rsqrtf(var + EPS_));
        }
        __syncthreads();
        for (int a = b2; a < 1024; a += AB)
            do_apply_item(x, out, s_wb, s_ms, N_ - 1, a);
    }
}

// ---------------------------------------------------------------------------
extern "C" void kernel_launch(void* const* d_in, const int* in_sizes, int n_in,
                              void* d_out, int out_size) {
    const float* x   = (const float*)d_in[0];
    const float* seg = (const float*)d_in[1];
    const float* wgt = (const float*)d_in[2];
    const float* bia = (const float*)d_in[3];
    float* out = (float*)d_out;

    spade_fused_kernel<<<GRID, THREADS>>>(x, seg, wgt, bia, out);
}